// round 16
// baseline (speedup 1.0000x reference)
#include <cuda_runtime.h>
#include <cuda_bf16.h>
#include <cstdint>

typedef unsigned int u32;
typedef unsigned long long u64;
typedef unsigned short u16;

#define GG 3
#define ZCAP 4096
#define ST 136                 // bf16 elements per padded tile row (272 B)
#define TILEB (128*ST*2)       // 34816 bytes per 128x128 bf16 tile
#define DYNSM (6*TILEB)        // 208896

// ---------------- device scratch (allocation-free, zero-init) ----------------
__device__ int   g_znum[24];
__device__ int   g_scan;
__device__ int   g_done;
__device__ int2  g_zlist[24*ZCAP];

// ---------------- helpers ----------------
static __device__ __forceinline__ u32 smem_u32(const void* p){
    u32 a;
    asm("{ .reg .u64 t; cvta.to.shared.u64 t, %1; cvt.u32.u64 %0, t; }" : "=r"(a) : "l"(p));
    return a;
}
#define LDSM_X4(r, a) \
    asm volatile("ldmatrix.sync.aligned.m8n8.x4.shared.b16 {%0,%1,%2,%3}, [%4];" \
        : "=r"((r)[0]),"=r"((r)[1]),"=r"((r)[2]),"=r"((r)[3]) : "r"(a))
#define LDSM_X4_T(r, a) \
    asm volatile("ldmatrix.sync.aligned.m8n8.x4.trans.shared.b16 {%0,%1,%2,%3}, [%4];" \
        : "=r"((r)[0]),"=r"((r)[1]),"=r"((r)[2]),"=r"((r)[3]) : "r"(a))

static __device__ __forceinline__ void mma16816(float* c, const u32* a, const u32* b){
    asm volatile("mma.sync.aligned.m16n8k16.row.col.f32.bf16.bf16.f32 "
        "{%0,%1,%2,%3}, {%4,%5,%6,%7}, {%8,%9}, {%0,%1,%2,%3};"
        : "+f"(c[0]),"+f"(c[1]),"+f"(c[2]),"+f"(c[3])
        : "r"(a[0]),"r"(a[1]),"r"(a[2]),"r"(a[3]), "r"(b[0]),"r"(b[1]));
}
// truncation split of two floats: h = packed bf16 hi (exact truncation),
// l = packed bf16 of exact residuals. a -> low half, b -> high half.
static __device__ __forceinline__ void split2(float a, float b, u32& h, u32& l){
    u32 ua = __float_as_uint(a), ub = __float_as_uint(b);
    h = __byte_perm(ua, ub, 0x7632);
    float la = a - __uint_as_float(ua & 0xFFFF0000u);
    float lb = b - __uint_as_float(ub & 0xFFFF0000u);
    asm("cvt.rn.bf16x2.f32 %0, %1, %2;" : "=r"(l) : "f"(lb), "f"(la));
}
static __device__ __forceinline__ void pack4(float4 x, u64& hv, u64& lv){
    u32 h01, l01, h23, l23;
    split2(x.x, x.y, h01, l01);
    split2(x.z, x.w, h23, l23);
    hv = (u64)h01 | ((u64)h23 << 32);
    lv = (u64)l01 | ((u64)l23 << 32);
}
static __device__ __forceinline__ float bf2f(u32 bits16){ return __uint_as_float(bits16 << 16); }

static __device__ __forceinline__ float warp_sum(float v){
    #pragma unroll
    for (int off = 16; off; off >>= 1) v += __shfl_xor_sync(0xFFFFFFFFu, v, off);
    return v;
}

// non-trans gemm (A [m][k] rows, B [n][k] rows), 3 split products, warp 32x32 tile
static __device__ __forceinline__ void gemm_tile(float acc[2][4][4], u32 aH, u32 aL, u32 bH, u32 bL){
    #pragma unroll
    for (int ks = 0; ks < 8; ++ks){
        u32 ah[2][4], al[2][4], bh[2][4], bl[2][4];
        #pragma unroll
        for (int mi = 0; mi < 2; ++mi){
            LDSM_X4(ah[mi], aH + mi*(16*ST*2) + ks*32);
            LDSM_X4(al[mi], aL + mi*(16*ST*2) + ks*32);
        }
        #pragma unroll
        for (int nj = 0; nj < 2; ++nj){
            LDSM_X4(bh[nj], bH + nj*(16*ST*2) + ks*32);
            LDSM_X4(bl[nj], bL + nj*(16*ST*2) + ks*32);
        }
        #pragma unroll
        for (int mi = 0; mi < 2; ++mi)
        #pragma unroll
        for (int nj = 0; nj < 2; ++nj){
            mma16816(acc[mi][nj*2],   ah[mi], &bh[nj][0]);
            mma16816(acc[mi][nj*2+1], ah[mi], &bh[nj][2]);
        }
        #pragma unroll
        for (int mi = 0; mi < 2; ++mi)
        #pragma unroll
        for (int nj = 0; nj < 2; ++nj){
            mma16816(acc[mi][nj*2],   ah[mi], &bl[nj][0]);
            mma16816(acc[mi][nj*2+1], ah[mi], &bl[nj][2]);
        }
        #pragma unroll
        for (int mi = 0; mi < 2; ++mi)
        #pragma unroll
        for (int nj = 0; nj < 2; ++nj){
            mma16816(acc[mi][nj*2],   al[mi], &bh[nj][0]);
            mma16816(acc[mi][nj*2+1], al[mi], &bh[nj][2]);
        }
    }
}

// trans-B gemm (A [m][k] rows, B [k][n] rows via ldmatrix.trans)
static __device__ __forceinline__ void gemm_tile_tb(float acc[2][4][4], u32 aH, u32 aL, u32 bH, u32 bL){
    #pragma unroll
    for (int ks = 0; ks < 8; ++ks){
        u32 ah[2][4], al[2][4], bh[2][4], bl[2][4];
        #pragma unroll
        for (int mi = 0; mi < 2; ++mi){
            LDSM_X4(ah[mi], aH + mi*(16*ST*2) + ks*32);
            LDSM_X4(al[mi], aL + mi*(16*ST*2) + ks*32);
        }
        #pragma unroll
        for (int nj = 0; nj < 2; ++nj){
            LDSM_X4_T(bh[nj], bH + nj*32 + ks*(16*ST*2));
            LDSM_X4_T(bl[nj], bL + nj*32 + ks*(16*ST*2));
        }
        #pragma unroll
        for (int mi = 0; mi < 2; ++mi)
        #pragma unroll
        for (int nj = 0; nj < 2; ++nj){
            mma16816(acc[mi][nj*2],   ah[mi], &bh[nj][0]);
            mma16816(acc[mi][nj*2+1], ah[mi], &bh[nj][2]);
        }
        #pragma unroll
        for (int mi = 0; mi < 2; ++mi)
        #pragma unroll
        for (int nj = 0; nj < 2; ++nj){
            mma16816(acc[mi][nj*2],   ah[mi], &bl[nj][0]);
            mma16816(acc[mi][nj*2+1], ah[mi], &bl[nj][2]);
        }
        #pragma unroll
        for (int mi = 0; mi < 2; ++mi)
        #pragma unroll
        for (int nj = 0; nj < 2; ++nj){
            mma16816(acc[mi][nj*2],   al[mi], &bh[nj][0]);
            mma16816(acc[mi][nj*2+1], al[mi], &bh[nj][2]);
        }
    }
}

// -------- fused: scan -> Gram -> T1/T2 -> Q -> output -> zero-fix -> reset --------
__global__ void __launch_bounds__(512, 1) kfuse(const float* __restrict__ Y,
                                                const float* __restrict__ infos,
                                                const float* __restrict__ Wd,
                                                const float* __restrict__ bd,
                                                const float* __restrict__ Wn,
                                                const float* __restrict__ bn,
                                                float* __restrict__ out){
    extern __shared__ __align__(16) char smc[];
    __shared__ float sT1[128], sT2[128], sVec[128], sBase[128];
    __shared__ int   sUs[16];
    __shared__ int   sM;

    int bf = blockIdx.x, b = bf >> 4, f = bf & 15;
    int t = threadIdx.x, wid = t >> 5, lane = t & 31;
    int wm = wid & 3, wn = wid >> 2;
    int m0 = wm*32, n0 = wn*32;
    int g = lane >> 2, t4 = lane & 3;

    u32 sb = smem_u32(smc);
    u32 aBase = sb + (u32)(((m0 + (lane & 15))*ST + (lane >> 4)*8) * 2);
    u32 bBase = sb + (u32)(((n0 + (lane & 7) + ((lane >> 4) & 1)*8)*ST + ((lane >> 3) & 1)*8) * 2);
    u32 bToff = (u32)(((lane & 15)*ST + n0 + (lane >> 4)*8) * 2);

    if (t < 128){ sT1[t] = 0.0f; sT2[t] = 0.0f; }

    // ---- issue chunk-0 X prefetch first (latency hidden behind scan + WS build) ----
    int cr = t >> 2, uh = (t & 3)*32;
    const float* xrow = infos + (((size_t)b*128 + cr)*16 + f)*512 + uh;
    float4 pf[8];
    #pragma unroll
    for (int i = 0; i < 8; ++i) pf[i] = *reinterpret_cast<const float4*>(xrow + i*4);

    // ---- fused zero-scan: block bf scans Y float4s [bf*12288, (bf+1)*12288) ----
    {
        #pragma unroll 4
        for (int it = 0; it < 24; ++it){
            int z = bf*12288 + it*512 + t;
            float4 y4 = reinterpret_cast<const float4*>(Y)[
                (size_t)(((z >> 16)/GG)*16 + ((z >> 16)%GG))*65536 + (z & 65535)];
            int l = (z & 65535)*4;
            float vals[4] = {y4.x, y4.y, y4.z, y4.w};
            #pragma unroll
            for (int r = 0; r < 4; ++r){
                if (vals[r] == 0.0f){
                    int bg2 = z >> 16;
                    int pos = atomicAdd(&g_znum[bg2], 1);
                    if (pos < ZCAP) g_zlist[bg2*ZCAP + pos] = make_int2(l >> 9, (l & 511) + r);
                }
            }
        }
        __syncthreads();
        if (t == 0){
            __threadfence();
            atomicAdd(&g_scan, 1);
        }
    }

    // ---- WS = W1+W3 fp32 [128][129] at S4 (untouched during Gram) ----
    {
        float* sWS = reinterpret_cast<float*>(smc + 4*TILEB);
        int d = t >> 2, ch = (t & 3)*32;
        #pragma unroll
        for (int i = 0; i < 8; ++i){
            int c0 = ch + i*4;
            float4 a  = *reinterpret_cast<const float4*>(Wd + d*384 + c0);
            float4 c3 = *reinterpret_cast<const float4*>(Wd + d*384 + 256 + c0);
            sWS[d*129 + c0 + 0] = a.x + c3.x;
            sWS[d*129 + c0 + 1] = a.y + c3.y;
            sWS[d*129 + c0 + 2] = a.z + c3.z;
            sWS[d*129 + c0 + 3] = a.w + c3.w;
        }
    }

    // ---- Gram: 4 K-chunks, reg-prefetch, 1 sync/iter, buffers S0/S1 <-> S2/S3 ----
    float t2acc = 0.0f;
    float acc[2][4][4] = {};
    #pragma unroll
    for (int kk = 0; kk < 4; ++kk){
        u32 off = (kk & 1) ? 2u*TILEB : 0u;
        #pragma unroll
        for (int i = 0; i < 8; i += 2){
            int ul = uh + i*4;
            t2acc += pf[i].x + pf[i].y + pf[i].z + pf[i].w
                   + pf[i+1].x + pf[i+1].y + pf[i+1].z + pf[i+1].w;
            u64 h0, l0, h1, l1;
            pack4(pf[i], h0, l0);
            pack4(pf[i+1], h1, l1);
            *reinterpret_cast<ulonglong2*>(smc + off + (cr*ST + ul)*2) = make_ulonglong2(h0, h1);
            *reinterpret_cast<ulonglong2*>(smc + off + TILEB + (cr*ST + ul)*2) = make_ulonglong2(l0, l1);
        }
        __syncthreads();
        if (kk < 3){
            #pragma unroll
            for (int i = 0; i < 8; ++i) pf[i] = *reinterpret_cast<const float4*>(xrow + (kk+1)*128 + i*4);
        }
        gemm_tile(acc, aBase + off, aBase + off + TILEB, bBase + off, bBase + off + TILEB);
    }
    __syncthreads();
    // NOTE: S2/S3 holds chunk 3 == output v-tile 3 (preserved below)
    atomicAdd(&sT2[cr], t2acc);
    __syncthreads();

    // ---- T1 epilogue from Gram accumulators (WS @ S4) ----
    {
        const float* sWS = reinterpret_cast<const float*>(smc + 4*TILEB);
        #pragma unroll
        for (int mi = 0; mi < 2; ++mi){
            int r0 = m0 + mi*16 + g, r1 = r0 + 8;
            float s0 = 0.0f, s1 = 0.0f;
            #pragma unroll
            for (int ni = 0; ni < 4; ++ni){
                int col = n0 + ni*8 + 2*t4;
                s0 += acc[mi][ni][0]*sWS[r0*129 + col] + acc[mi][ni][1]*sWS[r0*129 + col + 1];
                s1 += acc[mi][ni][2]*sWS[r1*129 + col] + acc[mi][ni][3]*sWS[r1*129 + col + 1];
            }
            atomicAdd(&sT1[r0], s0);
            atomicAdd(&sT1[r1], s1);
        }
    }
    __syncthreads();
    if (t < 128) sVec[t] = sT1[t] + sT2[t] * bd[t];
    __syncthreads();

    // ---- Wn tiles (hi@S0, lo@S1) + BQ [c][e] rows (hi@S4, lo@S5; WS dead) ----
    {
        int o = t >> 2, ch = (t & 3)*32;
        #pragma unroll
        for (int i = 0; i < 8; ++i){
            int c0 = ch + i*4;
            float4 w = *reinterpret_cast<const float4*>(Wn + o*128 + c0);
            u64 hv, lv; pack4(w, hv, lv);
            *reinterpret_cast<u64*>(smc + (o*ST + c0)*2)         = hv;
            *reinterpret_cast<u64*>(smc + TILEB + (o*ST + c0)*2) = lv;
        }
    }
    {
        int c = t >> 2, eb = (t & 3)*32;
        float t2c = sT2[c];
        #pragma unroll
        for (int i = 0; i < 8; ++i){
            int e0 = eb + i*4;
            float4 a  = *reinterpret_cast<const float4*>(Wd + c*384 + 128 + e0);
            float4 c3 = *reinterpret_cast<const float4*>(Wd + c*384 + 256 + e0);
            float4 v4 = make_float4(t2c*(a.x - c3.x), t2c*(a.y - c3.y), t2c*(a.z - c3.z), t2c*(a.w - c3.w));
            u64 hv, lv; pack4(v4, hv, lv);
            *reinterpret_cast<u64*>(smc + 4*TILEB + (c*ST + e0)*2) = hv;
            *reinterpret_cast<u64*>(smc + 5*TILEB + (c*ST + e0)*2) = lv;
        }
    }
    __syncthreads();

    // ---- k0[o] (t<128, from Wn smem) then Q gemm (all warps) ----
    float ksum = 0.0f;
    if (t < 128){
        #pragma unroll 4
        for (int c2 = 0; c2 < 128; c2 += 2){
            u32 hw = *reinterpret_cast<const u32*>(smc + (t*ST + c2)*2);
            u32 lw = *reinterpret_cast<const u32*>(smc + TILEB + (t*ST + c2)*2);
            float w0 = bf2f(hw & 0xffff) + bf2f(lw & 0xffff);
            float w1 = bf2f(hw >> 16)    + bf2f(lw >> 16);
            ksum += w0*sVec[c2] + w1*sVec[c2 + 1];
        }
    }
    float qacc[2][4][4] = {};
    gemm_tile_tb(qacc, aBase, aBase + TILEB, sb + 4*TILEB + bToff, sb + 5*TILEB + bToff);
    __syncthreads();

    // ---- Q epilogue: scale by 1/512 (exact), split to bf16 hi/lo into S0/S1 ----
    const float inv = 1.0f/512.0f;
    #pragma unroll
    for (int mi = 0; mi < 2; ++mi){
        int r0 = m0 + mi*16 + g, r1 = r0 + 8;
        #pragma unroll
        for (int ni = 0; ni < 4; ++ni){
            int col = n0 + ni*8 + 2*t4;
            u32 h01, l01;
            split2(qacc[mi][ni][0]*inv, qacc[mi][ni][1]*inv, h01, l01);
            *reinterpret_cast<u32*>(smc + (r0*ST + col)*2)         = h01;
            *reinterpret_cast<u32*>(smc + TILEB + (r0*ST + col)*2) = l01;
            split2(qacc[mi][ni][2]*inv, qacc[mi][ni][3]*inv, h01, l01);
            *reinterpret_cast<u32*>(smc + (r1*ST + col)*2)         = h01;
            *reinterpret_cast<u32*>(smc + TILEB + (r1*ST + col)*2) = l01;
        }
    }
    if (t < 128) sBase[t] = ksum*inv + bn[t];

    // prefetch vt0 for the output loop (S2/S3 already holds vt3)
    #pragma unroll
    for (int i = 0; i < 8; ++i) pf[i] = *reinterpret_cast<const float4*>(xrow + i*4);
    __syncthreads();

    // ---- output loop, tile order {3,0,1,2}, double-buffered S2/S3 <-> S4/S5 ----
    #pragma unroll
    for (int it = 0; it < 4; ++it){
        const int ord[4] = {3,0,1,2};
        int vt = ord[it];
        u32 curB = sb + (2 + 2*(it & 1))*TILEB + bToff;
        u32 othW = (2 + 2*((it + 1) & 1))*TILEB;
        if (it < 3){
            #pragma unroll
            for (int i = 0; i < 8; i += 2){
                int vl = uh + i*4;
                u64 h0, l0, h1, l1;
                pack4(pf[i], h0, l0);
                pack4(pf[i+1], h1, l1);
                *reinterpret_cast<ulonglong2*>(smc + othW + (cr*ST + vl)*2) = make_ulonglong2(h0, h1);
                *reinterpret_cast<ulonglong2*>(smc + othW + TILEB + (cr*ST + vl)*2) = make_ulonglong2(l0, l1);
            }
            if (it < 2){
                #pragma unroll
                for (int i = 0; i < 8; ++i) pf[i] = *reinterpret_cast<const float4*>(xrow + ord[it+2]*128 + i*4);
            }
        }

        float acc2[2][4][4] = {};
        gemm_tile_tb(acc2, aBase, aBase + TILEB, curB, curB + TILEB);

        int v0 = vt*128;
        #pragma unroll
        for (int mi = 0; mi < 2; ++mi){
            int o0 = m0 + mi*16 + g, o1 = o0 + 8;
            size_t base0 = ((size_t)(b*128 + o0)*16 + f)*512 + v0;
            size_t base1 = ((size_t)(b*128 + o1)*16 + f)*512 + v0;
            #pragma unroll
            for (int ni = 0; ni < 4; ++ni){
                int vc = n0 + ni*8 + 2*t4;
                float2 r0v, r1v;
                r0v.x = fmaxf(acc2[mi][ni][0] + sBase[o0], 0.0f);
                r0v.y = fmaxf(acc2[mi][ni][1] + sBase[o0], 0.0f);
                r1v.x = fmaxf(acc2[mi][ni][2] + sBase[o1], 0.0f);
                r1v.y = fmaxf(acc2[mi][ni][3] + sBase[o1], 0.0f);
                *reinterpret_cast<float2*>(out + base0 + vc) = r0v;
                *reinterpret_cast<float2*>(out + base1 + vc) = r1v;
            }
        }
        __syncthreads();
    }

    // ---- wait for chip-wide scan completion (long since done by now) ----
    if (t == 0){
        while (atomicAdd(&g_scan, 0) < 128) __nanosleep(200);
    }
    __syncthreads();
    __threadfence();

    // ---- tail: exact fix of zero-affected columns for this (b,f); weights L2-hot ----
    {
        int gz = (f == 0) ? 0 : ((f <= 11) ? 1 : 2);
        int bg = b*GG + gz;
        int nz = g_znum[bg]; if (nz > ZCAP) nz = ZCAP;
        if (nz > 0){
            float* sXv  = reinterpret_cast<float*>(smc);          // Q region dead
            float* sAgg = sXv + 128;
            float* sXu  = sAgg + 128;                              // [16][128]

            for (int i = 0; i < nz; ++i){
                int vz = g_zlist[bg*ZCAP + i].y;
                bool dup = false;
                for (int jj = 0; jj < i; ++jj)
                    if (g_zlist[bg*ZCAP + jj].y == vz){ dup = true; break; }
                if (dup) continue;

                if (t == 0){
                    int m = 0, mc = 0;
                    for (int jj = i; jj < nz; ++jj){
                        int2 e2 = g_zlist[bg*ZCAP + jj];
                        if (e2.y == vz){
                            if (mc < 16) sUs[mc++] = e2.x;
                            ++m;
                        }
                    }
                    sM = (mc << 16) | m;
                }
                __syncthreads();
                int m_full = sM & 0xFFFF;
                int m = sM >> 16;

                if (t < 128){
                    sXv[t] = infos[(size_t)(b*2048 + t*16 + f)*512 + vz];
                    for (int k = 0; k < m; ++k)
                        sXu[k*128 + t] = infos[(size_t)(b*2048 + t*16 + f)*512 + sUs[k]];
                }
                __syncthreads();

                // agg rows: 16 warps x 8 rows; lanes cover e (coalesced float4, L2-hot)
                #pragma unroll 2
                for (int r = 0; r < 8; ++r){
                    int c = wid*8 + r;
                    float4 w1 = *reinterpret_cast<const float4*>(Wd + c*384 + lane*4);
                    float4 w2 = *reinterpret_cast<const float4*>(Wd + c*384 + 128 + lane*4);
                    float4 w3 = *reinterpret_cast<const float4*>(Wd + c*384 + 256 + lane*4);
                    float ws0 = w1.x + w3.x, ws1 = w1.y + w3.y, ws2 = w1.z + w3.z, ws3 = w1.w + w3.w;
                    float4 xv = *reinterpret_cast<const float4*>(&sXv[lane*4]);
                    float dv = (w2.x - w3.x)*xv.x + (w2.y - w3.y)*xv.y
                             + (w2.z - w3.z)*xv.z + (w2.w - w3.w)*xv.w;
                    dv = warp_sum(dv);

                    float a1 = sT1[c];
                    float a2 = sT2[c];
                    for (int k = 0; k < m; ++k){
                        float4 xu = *reinterpret_cast<const float4*>(&sXu[k*128 + lane*4]);
                        float su = ws0*xu.x + ws1*xu.y + ws2*xu.z + ws3*xu.w;
                        su = warp_sum(su);
                        float xuc = sXu[k*128 + c];
                        a1 -= xuc * su;
                        a2 -= xuc;
                    }
                    if (lane == 0){
                        int degi = 512 - m_full;
                        float deg = (float)(degi > 1 ? degi : 1);
                        sAgg[c] = (a1 + a2*(dv + bd[c])) / deg;
                    }
                }
                __syncthreads();

                // output rows: 16 warps x 8 rows
                #pragma unroll 2
                for (int r = 0; r < 8; ++r){
                    int o = wid*8 + r;
                    float4 wnv = *reinterpret_cast<const float4*>(Wn + o*128 + lane*4);
                    float4 ag  = *reinterpret_cast<const float4*>(&sAgg[lane*4]);
                    float s = wnv.x*ag.x + wnv.y*ag.y + wnv.z*ag.z + wnv.w*ag.w;
                    s = warp_sum(s);
                    if (lane == 0)
                        out[(size_t)(b*2048 + o*16 + f)*512 + vz] = fmaxf(s + bn[o], 0.0f);
                }
                __syncthreads();
            }
        }
    }

    // ---- state reset for next graph replay: last block zeroes counters ----
    __syncthreads();
    if (t == 0){
        __threadfence();
        int done = atomicAdd(&g_done, 1);
        if (done == (int)gridDim.x - 1){
            #pragma unroll
            for (int i = 0; i < 24; ++i) g_znum[i] = 0;
            g_scan = 0;
            __threadfence();
            g_done = 0;
        }
    }
}

extern "C" void kernel_launch(void* const* d_in, const int* in_sizes, int n_in,
                              void* d_out, int out_size){
    const float* Y     = (const float*)d_in[0];
    const float* infos = (const float*)d_in[1];
    const float* Wd    = (const float*)d_in[2];
    const float* bd    = (const float*)d_in[3];
    const float* Wn    = (const float*)d_in[4];
    const float* bn    = (const float*)d_in[5];
    float* out = (float*)d_out;

    cudaFuncSetAttribute(kfuse, cudaFuncAttributeMaxDynamicSharedMemorySize, DYNSM);

    kfuse<<<128, 512, DYNSM>>>(Y, infos, Wd, bd, Wn, bn, out);
}

// round 17
// speedup vs baseline: 1.2000x; 1.2000x over previous
#include <cuda_runtime.h>
#include <cuda_bf16.h>
#include <cstdint>

typedef unsigned int u32;
typedef unsigned long long u64;
typedef unsigned short u16;

#define GG 3
#define ZCAP 4096
#define ST 136                 // bf16 elements per padded tile row (272 B)
#define TILEB (128*ST*2)       // 34816 bytes per 128x128 bf16 tile
#define DYNSM (6*TILEB)        // 208896

// ---------------- device scratch (allocation-free, zero-init) ----------------
__device__ int   g_znum[24];
__device__ int   g_scan;
__device__ int   g_done;
__device__ int2  g_zlist[24*ZCAP];

// ---------------- helpers ----------------
static __device__ __forceinline__ u32 smem_u32(const void* p){
    u32 a;
    asm("{ .reg .u64 t; cvta.to.shared.u64 t, %1; cvt.u32.u64 %0, t; }" : "=r"(a) : "l"(p));
    return a;
}
#define LDSM_X4(r, a) \
    asm volatile("ldmatrix.sync.aligned.m8n8.x4.shared.b16 {%0,%1,%2,%3}, [%4];" \
        : "=r"((r)[0]),"=r"((r)[1]),"=r"((r)[2]),"=r"((r)[3]) : "r"(a))
#define LDSM_X4_T(r, a) \
    asm volatile("ldmatrix.sync.aligned.m8n8.x4.trans.shared.b16 {%0,%1,%2,%3}, [%4];" \
        : "=r"((r)[0]),"=r"((r)[1]),"=r"((r)[2]),"=r"((r)[3]) : "r"(a))

static __device__ __forceinline__ void mma16816(float* c, const u32* a, const u32* b){
    asm volatile("mma.sync.aligned.m16n8k16.row.col.f32.bf16.bf16.f32 "
        "{%0,%1,%2,%3}, {%4,%5,%6,%7}, {%8,%9}, {%0,%1,%2,%3};"
        : "+f"(c[0]),"+f"(c[1]),"+f"(c[2]),"+f"(c[3])
        : "r"(a[0]),"r"(a[1]),"r"(a[2]),"r"(a[3]), "r"(b[0]),"r"(b[1]));
}
// truncation split: h = packed bf16 hi (exact truncation), l = bf16 of residuals.
static __device__ __forceinline__ void split2(float a, float b, u32& h, u32& l){
    u32 ua = __float_as_uint(a), ub = __float_as_uint(b);
    h = __byte_perm(ua, ub, 0x7632);
    float la = a - __uint_as_float(ua & 0xFFFF0000u);
    float lb = b - __uint_as_float(ub & 0xFFFF0000u);
    asm("cvt.rn.bf16x2.f32 %0, %1, %2;" : "=r"(l) : "f"(lb), "f"(la));
}
static __device__ __forceinline__ void pack4(float4 x, u64& hv, u64& lv){
    u32 h01, l01, h23, l23;
    split2(x.x, x.y, h01, l01);
    split2(x.z, x.w, h23, l23);
    hv = (u64)h01 | ((u64)h23 << 32);
    lv = (u64)l01 | ((u64)l23 << 32);
}
static __device__ __forceinline__ float bf2f(u32 bits16){ return __uint_as_float(bits16 << 16); }

static __device__ __forceinline__ float warp_sum(float v){
    #pragma unroll
    for (int off = 16; off; off >>= 1) v += __shfl_xor_sync(0xFFFFFFFFu, v, off);
    return v;
}

// non-trans gemm, warp 32x16 tile: acc[mi][ni][4], 3 split products
static __device__ __forceinline__ void gemm32(float acc[2][2][4], u32 aH, u32 aL, u32 bH, u32 bL){
    #pragma unroll
    for (int ks = 0; ks < 8; ++ks){
        u32 ah[2][4], al[2][4], bh[4], bl[4];
        #pragma unroll
        for (int mi = 0; mi < 2; ++mi){
            LDSM_X4(ah[mi], aH + mi*(16*ST*2) + ks*32);
            LDSM_X4(al[mi], aL + mi*(16*ST*2) + ks*32);
        }
        LDSM_X4(bh, bH + ks*32);
        LDSM_X4(bl, bL + ks*32);
        #pragma unroll
        for (int mi = 0; mi < 2; ++mi){
            mma16816(acc[mi][0], ah[mi], &bh[0]);
            mma16816(acc[mi][1], ah[mi], &bh[2]);
        }
        #pragma unroll
        for (int mi = 0; mi < 2; ++mi){
            mma16816(acc[mi][0], ah[mi], &bl[0]);
            mma16816(acc[mi][1], ah[mi], &bl[2]);
        }
        #pragma unroll
        for (int mi = 0; mi < 2; ++mi){
            mma16816(acc[mi][0], al[mi], &bh[0]);
            mma16816(acc[mi][1], al[mi], &bh[2]);
        }
    }
}

// trans-B gemm, warp 32x16 tile (B [k][n] rows via ldmatrix.trans)
static __device__ __forceinline__ void gemm32_tb(float acc[2][2][4], u32 aH, u32 aL, u32 bH, u32 bL){
    #pragma unroll
    for (int ks = 0; ks < 8; ++ks){
        u32 ah[2][4], al[2][4], bh[4], bl[4];
        #pragma unroll
        for (int mi = 0; mi < 2; ++mi){
            LDSM_X4(ah[mi], aH + mi*(16*ST*2) + ks*32);
            LDSM_X4(al[mi], aL + mi*(16*ST*2) + ks*32);
        }
        LDSM_X4_T(bh, bH + ks*(16*ST*2));
        LDSM_X4_T(bl, bL + ks*(16*ST*2));
        #pragma unroll
        for (int mi = 0; mi < 2; ++mi){
            mma16816(acc[mi][0], ah[mi], &bh[0]);
            mma16816(acc[mi][1], ah[mi], &bh[2]);
        }
        #pragma unroll
        for (int mi = 0; mi < 2; ++mi){
            mma16816(acc[mi][0], ah[mi], &bl[0]);
            mma16816(acc[mi][1], ah[mi], &bl[2]);
        }
        #pragma unroll
        for (int mi = 0; mi < 2; ++mi){
            mma16816(acc[mi][0], al[mi], &bh[0]);
            mma16816(acc[mi][1], al[mi], &bh[2]);
        }
    }
}

// -------- fused: scan -> Gram -> T1/T2 -> Q -> output -> zero-fix -> reset --------
__global__ void __launch_bounds__(1024, 1) kfuse(const float* __restrict__ Y,
                                                 const float* __restrict__ infos,
                                                 const float* __restrict__ Wd,
                                                 const float* __restrict__ bd,
                                                 const float* __restrict__ Wn,
                                                 const float* __restrict__ bn,
                                                 float* __restrict__ out){
    extern __shared__ __align__(16) char smc[];
    __shared__ float sT1[128], sT2[128], sVec[128], sBase[128];
    __shared__ int   sUs[16];
    __shared__ int   sM;

    int bf = blockIdx.x, b = bf >> 4, f = bf & 15;
    int t = threadIdx.x, wid = t >> 5, lane = t & 31;
    int wm = wid & 3, wn = wid >> 2;          // wn 0..7
    int m0 = wm*32, n0 = wn*16;
    int g = lane >> 2, t4 = lane & 3;

    u32 sb = smem_u32(smc);
    u32 aBase = sb + (u32)(((m0 + (lane & 15))*ST + (lane >> 4)*8) * 2);
    u32 bBase = sb + (u32)(((n0 + (lane & 7) + ((lane >> 4) & 1)*8)*ST + ((lane >> 3) & 1)*8) * 2);
    u32 bToff = (u32)(((lane & 15)*ST + n0 + (lane >> 4)*8) * 2);

    if (t < 128){ sT1[t] = 0.0f; sT2[t] = 0.0f; }

    // ---- chunk-0 X prefetch first (latency hidden behind scan + WS build) ----
    int cr = t >> 3, uh = (t & 7)*16;         // 8 threads/row, 16 floats each
    const float* xrow = infos + (((size_t)b*128 + cr)*16 + f)*512 + uh;
    float4 pf[4];
    #pragma unroll
    for (int i = 0; i < 4; ++i) pf[i] = *reinterpret_cast<const float4*>(xrow + i*4);

    // ---- fused zero-scan: block bf scans Y float4s [bf*12288, (bf+1)*12288) ----
    {
        #pragma unroll 4
        for (int it = 0; it < 12; ++it){
            int z = bf*12288 + it*1024 + t;
            float4 y4 = reinterpret_cast<const float4*>(Y)[
                (size_t)(((z >> 16)/GG)*16 + ((z >> 16)%GG))*65536 + (z & 65535)];
            int l = (z & 65535)*4;
            float vals[4] = {y4.x, y4.y, y4.z, y4.w};
            #pragma unroll
            for (int r = 0; r < 4; ++r){
                if (vals[r] == 0.0f){
                    int bg2 = z >> 16;
                    int pos = atomicAdd(&g_znum[bg2], 1);
                    if (pos < ZCAP) g_zlist[bg2*ZCAP + pos] = make_int2(l >> 9, (l & 511) + r);
                }
            }
        }
        __syncthreads();
        if (t == 0){
            __threadfence();
            atomicAdd(&g_scan, 1);
        }
    }

    // ---- WS = W1+W3 fp32 [128][129] at S4 ----
    {
        float* sWS = reinterpret_cast<float*>(smc + 4*TILEB);
        int d = t >> 3, ch = (t & 7)*16;
        #pragma unroll
        for (int i = 0; i < 4; ++i){
            int c0 = ch + i*4;
            float4 a  = *reinterpret_cast<const float4*>(Wd + d*384 + c0);
            float4 c3 = *reinterpret_cast<const float4*>(Wd + d*384 + 256 + c0);
            sWS[d*129 + c0 + 0] = a.x + c3.x;
            sWS[d*129 + c0 + 1] = a.y + c3.y;
            sWS[d*129 + c0 + 2] = a.z + c3.z;
            sWS[d*129 + c0 + 3] = a.w + c3.w;
        }
    }

    // ---- Gram: 4 K-chunks, reg-prefetch, 1 sync/iter, buffers S0/S1 <-> S2/S3 ----
    float t2acc = 0.0f;
    float acc[2][2][4] = {};
    #pragma unroll
    for (int kk = 0; kk < 4; ++kk){
        u32 off = (kk & 1) ? 2u*TILEB : 0u;
        #pragma unroll
        for (int i = 0; i < 4; i += 2){
            int ul = uh + i*4;
            t2acc += pf[i].x + pf[i].y + pf[i].z + pf[i].w
                   + pf[i+1].x + pf[i+1].y + pf[i+1].z + pf[i+1].w;
            u64 h0, l0, h1, l1;
            pack4(pf[i], h0, l0);
            pack4(pf[i+1], h1, l1);
            *reinterpret_cast<ulonglong2*>(smc + off + (cr*ST + ul)*2) = make_ulonglong2(h0, h1);
            *reinterpret_cast<ulonglong2*>(smc + off + TILEB + (cr*ST + ul)*2) = make_ulonglong2(l0, l1);
        }
        __syncthreads();
        if (kk < 3){
            #pragma unroll
            for (int i = 0; i < 4; ++i) pf[i] = *reinterpret_cast<const float4*>(xrow + (kk+1)*128 + i*4);
        }
        gemm32(acc, aBase + off, aBase + off + TILEB, bBase + off, bBase + off + TILEB);
    }
    __syncthreads();
    // S2/S3 holds chunk 3 == output v-tile 3 (preserved below)
    atomicAdd(&sT2[cr], t2acc);
    __syncthreads();

    // ---- T1 epilogue from Gram accumulators (WS @ S4) ----
    {
        const float* sWS = reinterpret_cast<const float*>(smc + 4*TILEB);
        #pragma unroll
        for (int mi = 0; mi < 2; ++mi){
            int r0 = m0 + mi*16 + g, r1 = r0 + 8;
            float s0 = 0.0f, s1 = 0.0f;
            #pragma unroll
            for (int ni = 0; ni < 2; ++ni){
                int col = n0 + ni*8 + 2*t4;
                s0 += acc[mi][ni][0]*sWS[r0*129 + col] + acc[mi][ni][1]*sWS[r0*129 + col + 1];
                s1 += acc[mi][ni][2]*sWS[r1*129 + col] + acc[mi][ni][3]*sWS[r1*129 + col + 1];
            }
            atomicAdd(&sT1[r0], s0);
            atomicAdd(&sT1[r1], s1);
        }
    }
    __syncthreads();
    if (t < 128) sVec[t] = sT1[t] + sT2[t] * bd[t];
    __syncthreads();

    // ---- Wn tiles (hi@S0, lo@S1) + BQ [c][e] rows (hi@S4, lo@S5; WS dead) ----
    {
        int o = t >> 3, ch = (t & 7)*16;
        #pragma unroll
        for (int i = 0; i < 4; ++i){
            int c0 = ch + i*4;
            float4 w = *reinterpret_cast<const float4*>(Wn + o*128 + c0);
            u64 hv, lv; pack4(w, hv, lv);
            *reinterpret_cast<u64*>(smc + (o*ST + c0)*2)         = hv;
            *reinterpret_cast<u64*>(smc + TILEB + (o*ST + c0)*2) = lv;
        }
    }
    {
        int c = t >> 3, eb = (t & 7)*16;
        float t2c = sT2[c];
        #pragma unroll
        for (int i = 0; i < 4; ++i){
            int e0 = eb + i*4;
            float4 a  = *reinterpret_cast<const float4*>(Wd + c*384 + 128 + e0);
            float4 c3 = *reinterpret_cast<const float4*>(Wd + c*384 + 256 + e0);
            float4 v4 = make_float4(t2c*(a.x - c3.x), t2c*(a.y - c3.y), t2c*(a.z - c3.z), t2c*(a.w - c3.w));
            u64 hv, lv; pack4(v4, hv, lv);
            *reinterpret_cast<u64*>(smc + 4*TILEB + (c*ST + e0)*2) = hv;
            *reinterpret_cast<u64*>(smc + 5*TILEB + (c*ST + e0)*2) = lv;
        }
    }
    __syncthreads();

    // ---- k0[o] (t<128) then Q gemm (all warps) ----
    float ksum = 0.0f;
    if (t < 128){
        #pragma unroll 4
        for (int c2 = 0; c2 < 128; c2 += 2){
            u32 hw = *reinterpret_cast<const u32*>(smc + (t*ST + c2)*2);
            u32 lw = *reinterpret_cast<const u32*>(smc + TILEB + (t*ST + c2)*2);
            float w0 = bf2f(hw & 0xffff) + bf2f(lw & 0xffff);
            float w1 = bf2f(hw >> 16)    + bf2f(lw >> 16);
            ksum += w0*sVec[c2] + w1*sVec[c2 + 1];
        }
    }
    float qacc[2][2][4] = {};
    gemm32_tb(qacc, aBase, aBase + TILEB, sb + 4*TILEB + bToff, sb + 5*TILEB + bToff);
    __syncthreads();

    // ---- Q epilogue: scale 1/512 (exact), split to bf16 hi/lo into S0/S1 ----
    const float inv = 1.0f/512.0f;
    #pragma unroll
    for (int mi = 0; mi < 2; ++mi){
        int r0 = m0 + mi*16 + g, r1 = r0 + 8;
        #pragma unroll
        for (int ni = 0; ni < 2; ++ni){
            int col = n0 + ni*8 + 2*t4;
            u32 h01, l01;
            split2(qacc[mi][ni][0]*inv, qacc[mi][ni][1]*inv, h01, l01);
            *reinterpret_cast<u32*>(smc + (r0*ST + col)*2)         = h01;
            *reinterpret_cast<u32*>(smc + TILEB + (r0*ST + col)*2) = l01;
            split2(qacc[mi][ni][2]*inv, qacc[mi][ni][3]*inv, h01, l01);
            *reinterpret_cast<u32*>(smc + (r1*ST + col)*2)         = h01;
            *reinterpret_cast<u32*>(smc + TILEB + (r1*ST + col)*2) = l01;
        }
    }
    if (t < 128) sBase[t] = ksum*inv + bn[t];

    // prefetch vt0 for the output loop (S2/S3 already holds vt3)
    #pragma unroll
    for (int i = 0; i < 4; ++i) pf[i] = *reinterpret_cast<const float4*>(xrow + i*4);
    __syncthreads();

    // ---- output loop, tile order {3,0,1,2}, double-buffered S2/S3 <-> S4/S5 ----
    #pragma unroll
    for (int it = 0; it < 4; ++it){
        const int ord[4] = {3,0,1,2};
        int vt = ord[it];
        u32 curB = sb + (2 + 2*(it & 1))*TILEB + bToff;
        u32 othW = (2 + 2*((it + 1) & 1))*TILEB;
        if (it < 3){
            #pragma unroll
            for (int i = 0; i < 4; i += 2){
                int vl = uh + i*4;
                u64 h0, l0, h1, l1;
                pack4(pf[i], h0, l0);
                pack4(pf[i+1], h1, l1);
                *reinterpret_cast<ulonglong2*>(smc + othW + (cr*ST + vl)*2) = make_ulonglong2(h0, h1);
                *reinterpret_cast<ulonglong2*>(smc + othW + TILEB + (cr*ST + vl)*2) = make_ulonglong2(l0, l1);
            }
            if (it < 2){
                #pragma unroll
                for (int i = 0; i < 4; ++i) pf[i] = *reinterpret_cast<const float4*>(xrow + ord[it+2]*128 + i*4);
            }
        }

        float acc2[2][2][4] = {};
        gemm32_tb(acc2, aBase, aBase + TILEB, curB, curB + TILEB);

        int v0 = vt*128;
        #pragma unroll
        for (int mi = 0; mi < 2; ++mi){
            int o0 = m0 + mi*16 + g, o1 = o0 + 8;
            size_t base0 = ((size_t)(b*128 + o0)*16 + f)*512 + v0;
            size_t base1 = ((size_t)(b*128 + o1)*16 + f)*512 + v0;
            #pragma unroll
            for (int ni = 0; ni < 2; ++ni){
                int vc = n0 + ni*8 + 2*t4;
                float2 r0v, r1v;
                r0v.x = fmaxf(acc2[mi][ni][0] + sBase[o0], 0.0f);
                r0v.y = fmaxf(acc2[mi][ni][1] + sBase[o0], 0.0f);
                r1v.x = fmaxf(acc2[mi][ni][2] + sBase[o1], 0.0f);
                r1v.y = fmaxf(acc2[mi][ni][3] + sBase[o1], 0.0f);
                *reinterpret_cast<float2*>(out + base0 + vc) = r0v;
                *reinterpret_cast<float2*>(out + base1 + vc) = r1v;
            }
        }
        __syncthreads();
    }

    // ---- wait for chip-wide scan completion (long since done by now) ----
    if (t == 0){
        while (atomicAdd(&g_scan, 0) < 128) __nanosleep(200);
    }
    __syncthreads();
    __threadfence();

    // ---- tail: exact fix of zero-affected columns for this (b,f) ----
    {
        int gz = (f == 0) ? 0 : ((f <= 11) ? 1 : 2);
        int bg = b*GG + gz;
        int nz = g_znum[bg]; if (nz > ZCAP) nz = ZCAP;
        if (nz > 0){
            float* sXv  = reinterpret_cast<float*>(smc);
            float* sAgg = sXv + 128;
            float* sXu  = sAgg + 128;                              // [16][128]

            for (int i = 0; i < nz; ++i){
                int vz = g_zlist[bg*ZCAP + i].y;
                bool dup = false;
                for (int jj = 0; jj < i; ++jj)
                    if (g_zlist[bg*ZCAP + jj].y == vz){ dup = true; break; }
                if (dup) continue;

                if (t == 0){
                    int m = 0, mc = 0;
                    for (int jj = i; jj < nz; ++jj){
                        int2 e2 = g_zlist[bg*ZCAP + jj];
                        if (e2.y == vz){
                            if (mc < 16) sUs[mc++] = e2.x;
                            ++m;
                        }
                    }
                    sM = (mc << 16) | m;
                }
                __syncthreads();
                int m_full = sM & 0xFFFF;
                int m = sM >> 16;

                if (t < 128){
                    sXv[t] = infos[(size_t)(b*2048 + t*16 + f)*512 + vz];
                    for (int k = 0; k < m; ++k)
                        sXu[k*128 + t] = infos[(size_t)(b*2048 + t*16 + f)*512 + sUs[k]];
                }
                __syncthreads();

                // agg rows: 32 warps x 4 rows; lanes cover e (coalesced float4)
                #pragma unroll
                for (int r = 0; r < 4; ++r){
                    int c = wid*4 + r;
                    float4 w1 = *reinterpret_cast<const float4*>(Wd + c*384 + lane*4);
                    float4 w2 = *reinterpret_cast<const float4*>(Wd + c*384 + 128 + lane*4);
                    float4 w3 = *reinterpret_cast<const float4*>(Wd + c*384 + 256 + lane*4);
                    float ws0 = w1.x + w3.x, ws1 = w1.y + w3.y, ws2 = w1.z + w3.z, ws3 = w1.w + w3.w;
                    float4 xv = *reinterpret_cast<const float4*>(&sXv[lane*4]);
                    float dv = (w2.x - w3.x)*xv.x + (w2.y - w3.y)*xv.y
                             + (w2.z - w3.z)*xv.z + (w2.w - w3.w)*xv.w;
                    dv = warp_sum(dv);

                    float a1 = sT1[c];
                    float a2 = sT2[c];
                    for (int k = 0; k < m; ++k){
                        float4 xu = *reinterpret_cast<const float4*>(&sXu[k*128 + lane*4]);
                        float su = ws0*xu.x + ws1*xu.y + ws2*xu.z + ws3*xu.w;
                        su = warp_sum(su);
                        float xuc = sXu[k*128 + c];
                        a1 -= xuc * su;
                        a2 -= xuc;
                    }
                    if (lane == 0){
                        int degi = 512 - m_full;
                        float deg = (float)(degi > 1 ? degi : 1);
                        sAgg[c] = (a1 + a2*(dv + bd[c])) / deg;
                    }
                }
                __syncthreads();

                // output rows: 32 warps x 4 rows
                #pragma unroll
                for (int r = 0; r < 4; ++r){
                    int o = wid*4 + r;
                    float4 wnv = *reinterpret_cast<const float4*>(Wn + o*128 + lane*4);
                    float4 ag  = *reinterpret_cast<const float4*>(&sAgg[lane*4]);
                    float s = wnv.x*ag.x + wnv.y*ag.y + wnv.z*ag.z + wnv.w*ag.w;
                    s = warp_sum(s);
                    if (lane == 0)
                        out[(size_t)(b*2048 + o*16 + f)*512 + vz] = fmaxf(s + bn[o], 0.0f);
                }
                __syncthreads();
            }
        }
    }

    // ---- state reset for next graph replay ----
    __syncthreads();
    if (t == 0){
        __threadfence();
        int done = atomicAdd(&g_done, 1);
        if (done == (int)gridDim.x - 1){
            #pragma unroll
            for (int i = 0; i < 24; ++i) g_znum[i] = 0;
            g_scan = 0;
            __threadfence();
            g_done = 0;
        }
    }
}

extern "C" void kernel_launch(void* const* d_in, const int* in_sizes, int n_in,
                              void* d_out, int out_size){
    const float* Y     = (const float*)d_in[0];
    const float* infos = (const float*)d_in[1];
    const float* Wd    = (const float*)d_in[2];
    const float* bd    = (const float*)d_in[3];
    const float* Wn    = (const float*)d_in[4];
    const float* bn    = (const float*)d_in[5];
    float* out = (float*)d_out;

    cudaFuncSetAttribute(kfuse, cudaFuncAttributeMaxDynamicSharedMemorySize, DYNSM);

    kfuse<<<128, 1024, DYNSM>>>(Y, infos, Wd, bd, Wn, bn, out);
}